// round 16
// baseline (speedup 1.0000x reference)
#include <cuda_runtime.h>
#include <cuda_fp16.h>
#include <cstdint>
#include <math.h>

// ===========================================================================
// TRAlign on mma.sync (HMMA) tensor cores — sm_103-safe baseline PTX only.
// All GEMMs fp16 inputs, fp32 accumulate (HMMA.16816.F32 rt=16 -> ~318 TF/s
// chip ceiling; big GEMMs run at it; floor = 365 GF -> ~1140 us).
//   2-term split [hi|lo]x[hi|hi] (~2^-12): Q proj, resid proj
//   1-term plain fp16:                     K proj, scores, V^T proj, ctx, out
// Softmax fused into GEMM epilogues (exp + atomic rowsum / rowdiv).
// wq/wk stored head-padded (N=256 = 4 heads x 64) -> no qk_split.
// V^T computed per head (4 launches) and ctx per (head, M-half) so each ctx
// piece starts as soon as ITS head's V^T is done (kills the 250 us false
// dependency). ln_A/out_A on s1 overlap the ctx B-halves.
// ===========================================================================

#define NQ 4096
#define LD 3584
#define RD 144
#define NH 4
#define HD 36
#define VHD 896

#define KP_RD   320
#define KP_HD   64

// ---------------- device scratch ----------------
__device__ __align__(128) __half g_te [(size_t)NQ * KP_RD];
__device__ __align__(128) __half g_se [(size_t)NQ * LD];
__device__ __align__(128) __half g_ve [(size_t)NQ * LD];
__device__ __align__(128) __half g_wqe[(size_t)256 * KP_RD];
__device__ __align__(128) __half g_wke[(size_t)256 * LD];
__device__ __align__(128) __half g_wve[(size_t)NH * VHD * LD];
__device__ __align__(128) __half g_re [(size_t)LD * KP_RD];
__device__ __align__(128) __half g_oe [(size_t)LD * LD];
__device__ __align__(128) float  g_rb [512];                      // remapped wq_b | wk_b
__device__ __align__(128) float  g_Kf [(size_t)NQ * 256];
__device__ __align__(128) __half g_Qe [(size_t)NQ * 256];         // Q head-layout fp16
__device__ __align__(128) __half g_Ke [(size_t)NQ * 256];         // K head-layout fp16
__device__ __align__(128) __half g_S  [(size_t)NH * NQ * NQ];     // exp(scores) fp16
__device__ __align__(128) float  g_sum[(size_t)NH * NQ];          // softmax row sums
__device__ __align__(128) __half g_Vte[(size_t)NH * VHD * NQ];    // V^T fp16 (direct)
__device__ __align__(128) float  g_Xf [(size_t)NQ * LD];
__device__ __align__(128) __half g_Xe [(size_t)NQ * LD];

// ---------------- PTX helpers (baseline, sm_80+) ----------------
__device__ __forceinline__ uint32_t smem_u32_of(const void* p) {
    uint32_t a;
    asm("{ .reg .u64 t; cvta.to.shared.u64 t, %1; cvt.u32.u64 %0, t; }"
        : "=r"(a) : "l"(p));
    return a;
}

__device__ __forceinline__ void cp16(uint32_t dst, const void* src) {
    asm volatile("cp.async.cg.shared.global [%0], [%1], 16;" :: "r"(dst), "l"(src));
}
__device__ __forceinline__ void cp_commit() {
    asm volatile("cp.async.commit_group;");
}
__device__ __forceinline__ void cp_wait1() {
    asm volatile("cp.async.wait_group 1;");
}

__device__ __forceinline__ void ldsm4(uint32_t* r, uint32_t addr) {
    asm volatile("ldmatrix.sync.aligned.m8n8.x4.shared.b16 {%0,%1,%2,%3}, [%4];"
                 : "=r"(r[0]), "=r"(r[1]), "=r"(r[2]), "=r"(r[3]) : "r"(addr));
}

__device__ __forceinline__ void mma16816(float* c, const uint32_t* a,
                                         uint32_t b0, uint32_t b1) {
    asm volatile(
        "mma.sync.aligned.m16n8k16.row.col.f32.f16.f16.f32 "
        "{%0,%1,%2,%3}, {%4,%5,%6,%7}, {%8,%9}, {%0,%1,%2,%3};"
        : "+f"(c[0]), "+f"(c[1]), "+f"(c[2]), "+f"(c[3])
        : "r"(a[0]), "r"(a[1]), "r"(a[2]), "r"(a[3]), "r"(b0), "r"(b1));
}

// ---------------- fp16 split helpers ----------------
__device__ __forceinline__ __half h_hi(float f) { return __float2half(f); }
__device__ __forceinline__ __half h_lo(float f) {
    float hi = __half2float(__float2half(f));
    return __float2half(f - hi);
}

// ===========================================================================
// HMMA GEMM: C[M, N] = alpha * A @ B^T (+bias) (+C), optional split-K,
// optional fp16 output, optional per-row bias.
// EMODE: 0 = plain, 1 = exp(out) + atomic row sums, 2 = scale rows by
//        1/rowDiv[r] before accumulate.
// ===========================================================================
#define STAGE_BYTES 36864
#define NSTAGE 3
#define MMA_SMEM (NSTAGE * STAGE_BYTES)

__device__ __forceinline__ void load_stage(uint32_t sbase,
                                           const __half* A, const __half* B,
                                           int lda, int ldb, int row0, int col0, int k0,
                                           int tid)
{
#pragma unroll
    for (int i = 0; i < 4; i++) {
        int c = tid + i * 256;              // 0..1023
        int r = c >> 3, cc = c & 7;         // row, 16B chunk within 64-col tile
        cp16(sbase + r * 144 + cc * 16,
             A + (size_t)(row0 + r) * lda + k0 + cc * 8);
        cp16(sbase + 18432 + r * 144 + cc * 16,
             B + (size_t)(col0 + r) * ldb + k0 + cc * 8);
    }
}

template <int EMODE>
__global__ __launch_bounds__(256, 2)
void mma_gemm(const __half* __restrict__ A, const __half* __restrict__ B,
              void* __restrict__ Cv, int K, int lda, int ldb, int ldc,
              long long sA, long long sB, long long sC,
              float alpha, const float* __restrict__ bias, int biasN, long long sBias,
              int accum, int splitK, int outHalf, int biasRow,
              float* __restrict__ expSum, const float* __restrict__ rowDiv,
              long long sSum)
{
    extern __shared__ char smem[];
    const uint32_t sb = smem_u32_of(smem);
    const int tid = threadIdx.x;
    const int warp = tid >> 5, lane = tid & 31;
    const int wm = warp & 1;                // M half (64 rows)
    const int wn = warp >> 1;               // N quarter (32 cols)

    const int z = blockIdx.z;
    const int batch = z / splitK;
    const int split = z - batch * splitK;
    const int Keff = K / splitK;

    A += (size_t)batch * sA + (size_t)split * Keff;
    B += (size_t)batch * sB + (size_t)split * Keff;
    float* Cf = (float*)Cv + (size_t)batch * sC;
    __half* Ch = (__half*)Cv + (size_t)batch * sC;
    if (bias) bias += (size_t)batch * sBias;
    const int row0 = blockIdx.y * 128, col0 = blockIdx.x * 128;

    float acc[4][4][4];
#pragma unroll
    for (int i = 0; i < 4; i++)
#pragma unroll
        for (int j = 0; j < 4; j++)
#pragma unroll
            for (int v = 0; v < 4; v++) acc[i][j][v] = 0.f;

    const int KT = Keff >> 6;

    // prefetch NSTAGE-1 stages
#pragma unroll
    for (int s = 0; s < NSTAGE - 1; s++) {
        if (s < KT) load_stage(sb + s * STAGE_BYTES, A, B, lda, ldb, row0, col0, s * 64, tid);
        cp_commit();
    }

    const int lrow = lane & 15;
    const int lkof = (lane >> 4) * 16;

    for (int kt = 0; kt < KT; kt++) {
        cp_wait1();
        __syncthreads();

        int ldk = kt + NSTAGE - 1;
        if (ldk < KT)
            load_stage(sb + (ldk % NSTAGE) * STAGE_BYTES, A, B, lda, ldb, row0, col0, ldk * 64, tid);
        cp_commit();

        uint32_t abase = sb + (kt % NSTAGE) * STAGE_BYTES + (wm * 64) * 144;
        uint32_t bbase = sb + (kt % NSTAGE) * STAGE_BYTES + 18432 + (wn * 32) * 144;

#pragma unroll
        for (int k16 = 0; k16 < 4; k16++) {
            uint32_t a[4][4];
#pragma unroll
            for (int mf = 0; mf < 4; mf++)
                ldsm4(a[mf], abase + (mf * 16 + lrow) * 144 + k16 * 32 + lkof);
            uint32_t b[2][4];
#pragma unroll
            for (int nf2 = 0; nf2 < 2; nf2++)
                ldsm4(b[nf2], bbase + (nf2 * 16 + lrow) * 144 + k16 * 32 + lkof);
#pragma unroll
            for (int mf = 0; mf < 4; mf++)
#pragma unroll
                for (int nf = 0; nf < 4; nf++)
                    mma16816(acc[mf][nf], a[mf], b[nf >> 1][nf & 1], b[nf >> 1][2 + (nf & 1)]);
        }
    }

    // -------- epilogue --------
    const int qr = lane >> 2;
    const int qc = (lane & 3) * 2;

    float inv[4][2];
    if (EMODE == 2) {
#pragma unroll
        for (int mf = 0; mf < 4; mf++)
#pragma unroll
            for (int h = 0; h < 2; h++)
                inv[mf][h] = 1.f / rowDiv[(size_t)batch * sSum +
                                          row0 + wm * 64 + mf * 16 + qr + h * 8];
    }
    float rsum[4][2];
    if (EMODE == 1) {
#pragma unroll
        for (int mf = 0; mf < 4; mf++)
#pragma unroll
            for (int h = 0; h < 2; h++) rsum[mf][h] = 0.f;
    }

#pragma unroll
    for (int mf = 0; mf < 4; mf++) {
#pragma unroll
        for (int nf = 0; nf < 4; nf++) {
            int gr = row0 + wm * 64 + mf * 16 + qr;
            int gc = col0 + wn * 32 + nf * 8 + qc;
            float b0 = 0.f, b1 = 0.f;
            if (bias && split == 0 && !biasRow) {
                if (gc + 0 < biasN) b0 = bias[gc + 0];
                if (gc + 1 < biasN) b1 = bias[gc + 1];
            }
#pragma unroll
            for (int h = 0; h < 2; h++) {
                int r = gr + h * 8;
                float br = (bias && split == 0 && biasRow && r < biasN) ? bias[r] : 0.f;
                float v0 = alpha * acc[mf][nf][h * 2 + 0];
                float v1 = alpha * acc[mf][nf][h * 2 + 1];
                if (EMODE == 1) {
                    v0 = __expf(v0);
                    v1 = __expf(v1);
                    rsum[mf][h] += v0 + v1;
                }
                if (EMODE == 2) { v0 *= inv[mf][h]; v1 *= inv[mf][h]; }
                v0 += b0 + br;
                v1 += b1 + br;
                if (outHalf) {
                    __half2 o;
                    o.x = __float2half(v0);
                    o.y = __float2half(v1);
                    *(__half2*)(Ch + (size_t)r * ldc + gc) = o;
                } else {
                    float* cp = Cf + (size_t)r * ldc + gc;
                    if (splitK > 1) {
                        atomicAdd(cp + 0, v0);
                        atomicAdd(cp + 1, v1);
                    } else {
                        if (accum) { v0 += cp[0]; v1 += cp[1]; }
                        float2 o = make_float2(v0, v1);
                        *(float2*)cp = o;
                    }
                }
            }
        }
    }

    if (EMODE == 1) {
#pragma unroll
        for (int mf = 0; mf < 4; mf++)
#pragma unroll
            for (int h = 0; h < 2; h++) {
                float s = rsum[mf][h];
                s += __shfl_xor_sync(0xffffffffu, s, 1);
                s += __shfl_xor_sync(0xffffffffu, s, 2);
                if ((lane & 3) == 0) {
                    int r = row0 + wm * 64 + mf * 16 + qr + h * 8;
                    atomicAdd(expSum + (size_t)batch * sSum + r, s);
                }
            }
    }
}

// ===========================================================================
// Conversion kernels
// ===========================================================================
__global__ void ext_rows(const float* __restrict__ in, __half* __restrict__ out,
                         int Kin, int ldin, int Kp, int terms, int loIdx)
{
    int c = blockIdx.x * 256 + threadIdx.x;
    if (c >= Kp) return;
    size_t row = blockIdx.y;
    int b = c / Kin;
    __half r;
    if (b >= terms) r = __float2half(0.f);
    else {
        float f = in[row * ldin + (c - b * Kin)];
        r = (b == loIdx) ? h_lo(f) : h_hi(f);
    }
    out[row * (size_t)Kp + c] = r;
}

// B-side transpose expansion with optional head remap:
// hs>0: out row n sources in column (n/hs)*hd + (n%hs), zero if (n%hs)>=hd.
__global__ void ext_transpose(const float* __restrict__ in, __half* __restrict__ out,
                              int Kin, int Nn, int Np, int Kp, int ldw,
                              long long sIn, long long sOut, int terms, int loIdx,
                              int hd, int hs)
{
    __shared__ float t[32][33];
    int b = blockIdx.z % terms, z = blockIdx.z / terms;
    in  += (size_t)z * sIn;
    out += (size_t)z * sOut;
    int k0 = blockIdx.x * 32, n0 = blockIdx.y * 32;
    int tx = threadIdx.x, ty = threadIdx.y;   // 32 x 8
#pragma unroll
    for (int i = 0; i < 4; i++) {
        int k = k0 + ty + i * 8, n = n0 + tx;
        int col; bool valid;
        if (hs > 0) {
            int dd = n % hs;
            col = (n / hs) * hd + dd;
            valid = (dd < hd) && (col < Nn);
        } else {
            col = n;
            valid = n < Nn;
        }
        t[ty + i * 8][tx] = (k < Kin && valid) ? in[(size_t)k * ldw + col] : 0.f;
    }
    __syncthreads();
#pragma unroll
    for (int i = 0; i < 4; i++) {
        int n = n0 + ty + i * 8, k = k0 + tx;
        if (n < Np && k < Kin) {
            float f = t[tx][ty + i * 8];
            out[(size_t)n * Kp + (size_t)b * Kin + k] = (b == loIdx) ? h_lo(f) : h_hi(f);
        }
    }
}

// Remap wq_b / wk_b into head-padded layout: rb[0:256]=wq_b, rb[256:512]=wk_b.
__global__ void bias_remap(const float* __restrict__ bq, const float* __restrict__ bk,
                           float* __restrict__ rb)
{
    int n = threadIdx.x;            // 256
    int dd = n & 63, h = n >> 6;
    float vq = (dd < HD) ? bq[h * HD + dd] : 0.f;
    float vk = (dd < HD) ? bk[h * HD + dd] : 0.f;
    rb[n] = vq;
    rb[256 + n] = vk;
}

// fp32 -> fp16 cast (vectorized), n % 1024 == 0.
__global__ void cast_f2h(const float* __restrict__ in, __half* __restrict__ out)
{
    int i = (blockIdx.x * 256 + threadIdx.x) * 4;
    float4 v = *(const float4*)(in + i);
    *(__half2*)(out + i)     = __floats2half2_rn(v.x, v.y);
    *(__half2*)(out + i + 2) = __floats2half2_rn(v.z, v.w);
}

// LayerNorm (row of 3584) fused with 1-term fp16 write into [*,3584].
__global__ __launch_bounds__(256)
void ln_ext(const float* __restrict__ X, __half* __restrict__ out,
            const float* __restrict__ g, const float* __restrict__ b)
{
    const int D = LD;
    const float* p = X + (size_t)blockIdx.x * D;
    __half* q = out + (size_t)blockIdx.x * D;
    const int t = threadIdx.x;
    float v[14];
    float s = 0.f;
#pragma unroll
    for (int i = 0; i < 14; i++) { v[i] = p[t + i * 256]; s += v[i]; }
    __shared__ float red[256];
    red[t] = s; __syncthreads();
#pragma unroll
    for (int st = 128; st > 0; st >>= 1) { if (t < st) red[t] += red[t + st]; __syncthreads(); }
    const float mean = red[0] / (float)D; __syncthreads();
    float sq = 0.f;
#pragma unroll
    for (int i = 0; i < 14; i++) { float d = v[i] - mean; sq += d * d; }
    red[t] = sq; __syncthreads();
#pragma unroll
    for (int st = 128; st > 0; st >>= 1) { if (t < st) red[t] += red[t + st]; __syncthreads(); }
    const float inv = rsqrtf(red[0] / (float)D + 1e-5f);
#pragma unroll
    for (int i = 0; i < 14; i++) {
        int c = t + i * 256;
        float y = (v[i] - mean) * inv * g[c] + b[c];
        q[c] = __float2half(y);
    }
}

// ===========================================================================
// Launcher — per-head V^T -> ctx pipelining; ln_A/out_A overlap ctx B-halves
// ===========================================================================
extern "C" void kernel_launch(void* const* d_in, const int* in_sizes, int n_in,
                              void* d_out, int out_size)
{
    const float* target  = (const float*)d_in[0];
    const float* source  = (const float*)d_in[1];
    const float* value   = (const float*)d_in[2];
    const float* wq_w    = (const float*)d_in[3];
    const float* wq_b    = (const float*)d_in[4];
    const float* wk_w    = (const float*)d_in[5];
    const float* wk_b    = (const float*)d_in[6];
    const float* wv_w    = (const float*)d_in[7];
    const float* wv_b    = (const float*)d_in[8];
    const float* resid_w = (const float*)d_in[9];
    const float* resid_b = (const float*)d_in[10];
    const float* out_w   = (const float*)d_in[11];
    const float* out_b   = (const float*)d_in[12];
    const float* ln_g    = (const float*)d_in[13];
    const float* ln_b    = (const float*)d_in[14];
    float* out = (float*)d_out;

    __half *pte, *pse, *pve, *pwqe, *pwke, *pwve, *pre, *poe;
    __half *pQe, *pKe, *pS, *pVte, *pXe;
    float *pKf, *pXf, *pSum, *prb;
    cudaGetSymbolAddress((void**)&pte, g_te);
    cudaGetSymbolAddress((void**)&pse, g_se);
    cudaGetSymbolAddress((void**)&pve, g_ve);
    cudaGetSymbolAddress((void**)&pwqe, g_wqe);
    cudaGetSymbolAddress((void**)&pwke, g_wke);
    cudaGetSymbolAddress((void**)&pwve, g_wve);
    cudaGetSymbolAddress((void**)&pre, g_re);
    cudaGetSymbolAddress((void**)&poe, g_oe);
    cudaGetSymbolAddress((void**)&prb, g_rb);
    cudaGetSymbolAddress((void**)&pKf, g_Kf);
    cudaGetSymbolAddress((void**)&pQe, g_Qe);
    cudaGetSymbolAddress((void**)&pKe, g_Ke);
    cudaGetSymbolAddress((void**)&pS, g_S);
    cudaGetSymbolAddress((void**)&pSum, g_sum);
    cudaGetSymbolAddress((void**)&pVte, g_Vte);
    cudaGetSymbolAddress((void**)&pXf, g_Xf);
    cudaGetSymbolAddress((void**)&pXe, g_Xe);

    cudaFuncSetAttribute(mma_gemm<0>, cudaFuncAttributeMaxDynamicSharedMemorySize, MMA_SMEM);
    cudaFuncSetAttribute(mma_gemm<1>, cudaFuncAttributeMaxDynamicSharedMemorySize, MMA_SMEM);
    cudaFuncSetAttribute(mma_gemm<2>, cudaFuncAttributeMaxDynamicSharedMemorySize, MMA_SMEM);

    static cudaStream_t s1 = 0, s2 = 0;
    static cudaEvent_t evFork = 0, evQp = 0, evResid = 0, evOE = 0;
    static cudaEvent_t evVt[4] = {0, 0, 0, 0};
    static cudaEvent_t evCtxA = 0, evOutA = 0;
    if (!evFork) {
        cudaStreamCreateWithFlags(&s1, cudaStreamNonBlocking);
        cudaStreamCreateWithFlags(&s2, cudaStreamNonBlocking);
        cudaEventCreateWithFlags(&evFork, cudaEventDisableTiming);
        cudaEventCreateWithFlags(&evQp, cudaEventDisableTiming);
        cudaEventCreateWithFlags(&evResid, cudaEventDisableTiming);
        cudaEventCreateWithFlags(&evOE, cudaEventDisableTiming);
        for (int h = 0; h < 4; h++) cudaEventCreateWithFlags(&evVt[h], cudaEventDisableTiming);
        cudaEventCreateWithFlags(&evCtxA, cudaEventDisableTiming);
        cudaEventCreateWithFlags(&evOutA, cudaEventDisableTiming);
    }

    // ---- fork ----
    cudaEventRecord(evFork, 0);
    cudaStreamWaitEvent(s1, evFork, 0);
    cudaStreamWaitEvent(s2, evFork, 0);

    // ===== stream s1: Q chain (head layout), resid chain, out_w ext ========
    cudaMemsetAsync(pwqe, 0, (size_t)256 * KP_RD * sizeof(__half), s1);
    cudaMemsetAsync(pre, 0, (size_t)LD * KP_RD * sizeof(__half), s1);
    ext_rows<<<dim3(2, NQ), 256, 0, s1>>>(target, pte, RD, RD, KP_RD, 2, 1);
    ext_transpose<<<dim3(5, 8, 2), dim3(32, 8), 0, s1>>>(
        wq_w, pwqe, RD, RD, 256, KP_RD, RD, 0, 0, 2, -1, HD, 64);          // head remap
    bias_remap<<<1, 256, 0, s1>>>(wq_b, wk_b, prb);
    mma_gemm<0><<<dim3(2, 32, 1), 256, MMA_SMEM, s1>>>(
        pte, pwqe, pQe, KP_RD, KP_RD, KP_RD, 256, 0, 0, 0, 1.f, prb, 256, 0, 0, 1, 1, 0,
        nullptr, nullptr, 0);                                              // fp16 head layout
    cudaEventRecord(evQp, s1);
    ext_transpose<<<dim3(5, 112, 2), dim3(32, 8), 0, s1>>>(
        resid_w, pre, RD, LD, LD, KP_RD, LD, 0, 0, 2, -1, 0, 0);
    mma_gemm<0><<<dim3(28, 32, 1), 256, MMA_SMEM, s1>>>(
        pte, pre, pXf, KP_RD, KP_RD, KP_RD, LD, 0, 0, 0, 1.f, resid_b, LD, 0, 0, 1, 0, 0,
        nullptr, nullptr, 0);
    cudaEventRecord(evResid, s1);
    ext_transpose<<<dim3(112, 112, 1), dim3(32, 8), 0, s1>>>(
        out_w, poe, LD, LD, LD, LD, LD, 0, 0, 1, -1, 0, 0);
    cudaEventRecord(evOE, s1);

    // ===== stream s2: V chain — per-head V^T with per-head events ==========
    ext_rows<<<dim3(14, NQ), 256, 0, s2>>>(value, pve, LD, LD, LD, 1, -1);
    ext_transpose<<<dim3(112, 28, 4), dim3(32, 8), 0, s2>>>(
        wv_w, pwve, LD, VHD, VHD, LD, VHD,
        (long long)LD * VHD, (long long)VHD * LD, 1, -1, 0, 0);
    for (int h = 0; h < NH; h++) {
        mma_gemm<0><<<dim3(32, 7, 1), 256, MMA_SMEM, s2>>>(
            pwve + (size_t)h * VHD * LD, pve, pVte + (size_t)h * VHD * NQ,
            LD, LD, LD, NQ, 0, 0, 0,
            1.f, wv_b + (size_t)h * VHD, VHD, 0, 0, 1, 1, 1,
            nullptr, nullptr, 0);
        cudaEventRecord(evVt[h], s2);
    }

    // ===== default stream: K chain + scores =====
    cudaMemsetAsync(pKf, 0, (size_t)NQ * 256 * sizeof(float), 0);
    cudaMemsetAsync(pSum, 0, (size_t)NH * NQ * sizeof(float), 0);
    ext_rows<<<dim3(14, NQ), 256, 0, 0>>>(source, pse, LD, LD, LD, 1, -1);
    ext_transpose<<<dim3(112, 8, 1), dim3(32, 8), 0, 0>>>(
        wk_w, pwke, LD, RD, 256, LD, RD, 0, 0, 1, -1, HD, 64);             // head remap
    mma_gemm<0><<<dim3(2, 32, 4), 256, MMA_SMEM, 0>>>(
        pse, pwke, pKf, LD, LD, LD, 256, 0, 0, 0, 1.f, prb + 256, 256, 0, 0, 4, 0, 0,
        nullptr, nullptr, 0);
    cast_f2h<<<NQ, 256, 0, 0>>>(pKf, pKe);

    cudaStreamWaitEvent(0, evQp, 0);
    // scores (all heads): S = exp(QK/6), fp16 + atomic rowsums
    mma_gemm<1><<<dim3(32, 32, NH), 256, MMA_SMEM, 0>>>(
        pQe, pKe, pS, KP_HD, 256, 256, NQ,
        64, 64, (long long)NQ * NQ,
        1.f / 6.f, nullptr, 0, 0, 0, 1, 1, 0,
        pSum, nullptr, NQ);

    // ===== ctx per (head, M-half): A-halves first, each gated on its V^T ===
    cudaStreamWaitEvent(0, evResid, 0);
    for (int h = 0; h < NH; h++) {
        cudaStreamWaitEvent(0, evVt[h], 0);
        mma_gemm<2><<<dim3(7, 16, 1), 256, MMA_SMEM, 0>>>(
            pS + (size_t)h * NQ * NQ, pVte + (size_t)h * VHD * NQ,
            pXf + (size_t)h * VHD, NQ, NQ, NQ, LD,
            0, 0, 0,
            1.f, nullptr, 0, 0, 1, 1, 0, 0,
            nullptr, pSum + (size_t)h * NQ, 0);
    }
    cudaEventRecord(evCtxA, 0);
    // B-halves (V^T deps already satisfied on stream 0)
    for (int h = 0; h < NH; h++) {
        mma_gemm<2><<<dim3(7, 16, 1), 256, MMA_SMEM, 0>>>(
            pS + (size_t)h * NQ * NQ + (size_t)2048 * NQ, pVte + (size_t)h * VHD * NQ,
            pXf + (size_t)h * VHD + (size_t)2048 * LD, NQ, NQ, NQ, LD,
            0, 0, 0,
            1.f, nullptr, 0, 0, 1, 1, 0, 0,
            nullptr, pSum + (size_t)h * NQ + 2048, 0);
    }

    // ===== s1: ln_A + out_A overlap ctx B-halves =====
    cudaStreamWaitEvent(s1, evCtxA, 0);
    ln_ext<<<2048, 256, 0, s1>>>(pXf, pXe, ln_g, ln_b);
    mma_gemm<0><<<dim3(28, 16, 1), 256, MMA_SMEM, s1>>>(
        pXe, poe, out, LD, LD, LD, LD, 0, 0, 0, 1.f, out_b, LD, 0, 0, 1, 0, 0,
        nullptr, nullptr, 0);
    cudaEventRecord(evOutA, s1);

    // ===== default stream: ln_B + out_B =====
    ln_ext<<<2048, 256, 0, 0>>>(pXf + (size_t)2048 * LD, pXe + (size_t)2048 * LD, ln_g, ln_b);
    cudaStreamWaitEvent(0, evOE, 0);
    mma_gemm<0><<<dim3(28, 16, 1), 256, MMA_SMEM, 0>>>(
        pXe + (size_t)2048 * LD, poe, out + (size_t)2048 * LD, LD, LD, LD, LD,
        0, 0, 0, 1.f, out_b, LD, 0, 0, 1, 0, 0,
        nullptr, nullptr, 0);

    // ---- join ----
    cudaStreamWaitEvent(0, evOutA, 0);
}

// round 17
// speedup vs baseline: 1.2722x; 1.2722x over previous
#include <cuda_runtime.h>
#include <cuda_fp16.h>
#include <cstdint>
#include <math.h>

// ===========================================================================
// TRAlign on mma.sync (HMMA) tensor cores — sm_103-safe baseline PTX only.
// All GEMMs fp16 inputs, fp32 accumulate (HMMA.16816.F32 rt=16 -> ~318 TF/s
// chip ceiling; big GEMMs run at it; floor = 365 GF -> ~1140 us).
//   2-term split [hi|lo]x[hi|hi] (~2^-12): Q proj, resid proj
//   1-term plain fp16:                     K proj, scores, V^T proj, ctx, out
// Softmax fused into GEMM epilogues (exp + atomic rowsum / rowdiv).
// wq/wk stored head-padded (N=256 = 4 heads x 64) -> no qk_split.
// scores M-split overlapped with ctx (R14 schedule = empirical best;
// finer-grained splits measured SLOWER due to wave quantization).
// source/value fp32->fp16 via vectorized cast_f2h (pure cast, 4 elem/thread).
// ===========================================================================

#define NQ 4096
#define LD 3584
#define RD 144
#define NH 4
#define HD 36
#define VHD 896

#define KP_RD   320
#define KP_HD   64

// ---------------- device scratch ----------------
__device__ __align__(128) __half g_te [(size_t)NQ * KP_RD];
__device__ __align__(128) __half g_se [(size_t)NQ * LD];
__device__ __align__(128) __half g_ve [(size_t)NQ * LD];
__device__ __align__(128) __half g_wqe[(size_t)256 * KP_RD];
__device__ __align__(128) __half g_wke[(size_t)256 * LD];
__device__ __align__(128) __half g_wve[(size_t)NH * VHD * LD];
__device__ __align__(128) __half g_re [(size_t)LD * KP_RD];
__device__ __align__(128) __half g_oe [(size_t)LD * LD];
__device__ __align__(128) float  g_rb [512];                      // remapped wq_b | wk_b
__device__ __align__(128) float  g_Kf [(size_t)NQ * 256];
__device__ __align__(128) __half g_Qe [(size_t)NQ * 256];         // Q head-layout fp16
__device__ __align__(128) __half g_Ke [(size_t)NQ * 256];         // K head-layout fp16
__device__ __align__(128) __half g_S  [(size_t)NH * NQ * NQ];     // exp(scores) fp16
__device__ __align__(128) float  g_sum[(size_t)NH * NQ];          // softmax row sums
__device__ __align__(128) __half g_Vte[(size_t)NH * VHD * NQ];    // V^T fp16 (direct)
__device__ __align__(128) float  g_Xf [(size_t)NQ * LD];
__device__ __align__(128) __half g_Xe [(size_t)NQ * LD];

// ---------------- PTX helpers (baseline, sm_80+) ----------------
__device__ __forceinline__ uint32_t smem_u32_of(const void* p) {
    uint32_t a;
    asm("{ .reg .u64 t; cvta.to.shared.u64 t, %1; cvt.u32.u64 %0, t; }"
        : "=r"(a) : "l"(p));
    return a;
}

__device__ __forceinline__ void cp16(uint32_t dst, const void* src) {
    asm volatile("cp.async.cg.shared.global [%0], [%1], 16;" :: "r"(dst), "l"(src));
}
__device__ __forceinline__ void cp_commit() {
    asm volatile("cp.async.commit_group;");
}
__device__ __forceinline__ void cp_wait1() {
    asm volatile("cp.async.wait_group 1;");
}

__device__ __forceinline__ void ldsm4(uint32_t* r, uint32_t addr) {
    asm volatile("ldmatrix.sync.aligned.m8n8.x4.shared.b16 {%0,%1,%2,%3}, [%4];"
                 : "=r"(r[0]), "=r"(r[1]), "=r"(r[2]), "=r"(r[3]) : "r"(addr));
}

__device__ __forceinline__ void mma16816(float* c, const uint32_t* a,
                                         uint32_t b0, uint32_t b1) {
    asm volatile(
        "mma.sync.aligned.m16n8k16.row.col.f32.f16.f16.f32 "
        "{%0,%1,%2,%3}, {%4,%5,%6,%7}, {%8,%9}, {%0,%1,%2,%3};"
        : "+f"(c[0]), "+f"(c[1]), "+f"(c[2]), "+f"(c[3])
        : "r"(a[0]), "r"(a[1]), "r"(a[2]), "r"(a[3]), "r"(b0), "r"(b1));
}

// ---------------- fp16 split helpers ----------------
__device__ __forceinline__ __half h_hi(float f) { return __float2half(f); }
__device__ __forceinline__ __half h_lo(float f) {
    float hi = __half2float(__float2half(f));
    return __float2half(f - hi);
}

// ===========================================================================
// HMMA GEMM: C[M, N] = alpha * A @ B^T (+bias) (+C), optional split-K,
// optional fp16 output, optional per-row bias.
// EMODE: 0 = plain, 1 = exp(out) + atomic row sums, 2 = scale rows by
//        1/rowDiv[r] before accumulate.
// ===========================================================================
#define STAGE_BYTES 36864
#define NSTAGE 3
#define MMA_SMEM (NSTAGE * STAGE_BYTES)

__device__ __forceinline__ void load_stage(uint32_t sbase,
                                           const __half* A, const __half* B,
                                           int lda, int ldb, int row0, int col0, int k0,
                                           int tid)
{
#pragma unroll
    for (int i = 0; i < 4; i++) {
        int c = tid + i * 256;              // 0..1023
        int r = c >> 3, cc = c & 7;         // row, 16B chunk within 64-col tile
        cp16(sbase + r * 144 + cc * 16,
             A + (size_t)(row0 + r) * lda + k0 + cc * 8);
        cp16(sbase + 18432 + r * 144 + cc * 16,
             B + (size_t)(col0 + r) * ldb + k0 + cc * 8);
    }
}

template <int EMODE>
__global__ __launch_bounds__(256, 2)
void mma_gemm(const __half* __restrict__ A, const __half* __restrict__ B,
              void* __restrict__ Cv, int K, int lda, int ldb, int ldc,
              long long sA, long long sB, long long sC,
              float alpha, const float* __restrict__ bias, int biasN, long long sBias,
              int accum, int splitK, int outHalf, int biasRow,
              float* __restrict__ expSum, const float* __restrict__ rowDiv,
              long long sSum)
{
    extern __shared__ char smem[];
    const uint32_t sb = smem_u32_of(smem);
    const int tid = threadIdx.x;
    const int warp = tid >> 5, lane = tid & 31;
    const int wm = warp & 1;                // M half (64 rows)
    const int wn = warp >> 1;               // N quarter (32 cols)

    const int z = blockIdx.z;
    const int batch = z / splitK;
    const int split = z - batch * splitK;
    const int Keff = K / splitK;

    A += (size_t)batch * sA + (size_t)split * Keff;
    B += (size_t)batch * sB + (size_t)split * Keff;
    float* Cf = (float*)Cv + (size_t)batch * sC;
    __half* Ch = (__half*)Cv + (size_t)batch * sC;
    if (bias) bias += (size_t)batch * sBias;
    const int row0 = blockIdx.y * 128, col0 = blockIdx.x * 128;

    float acc[4][4][4];
#pragma unroll
    for (int i = 0; i < 4; i++)
#pragma unroll
        for (int j = 0; j < 4; j++)
#pragma unroll
            for (int v = 0; v < 4; v++) acc[i][j][v] = 0.f;

    const int KT = Keff >> 6;

    // prefetch NSTAGE-1 stages
#pragma unroll
    for (int s = 0; s < NSTAGE - 1; s++) {
        if (s < KT) load_stage(sb + s * STAGE_BYTES, A, B, lda, ldb, row0, col0, s * 64, tid);
        cp_commit();
    }

    const int lrow = lane & 15;
    const int lkof = (lane >> 4) * 16;

    for (int kt = 0; kt < KT; kt++) {
        cp_wait1();
        __syncthreads();

        int ldk = kt + NSTAGE - 1;
        if (ldk < KT)
            load_stage(sb + (ldk % NSTAGE) * STAGE_BYTES, A, B, lda, ldb, row0, col0, ldk * 64, tid);
        cp_commit();

        uint32_t abase = sb + (kt % NSTAGE) * STAGE_BYTES + (wm * 64) * 144;
        uint32_t bbase = sb + (kt % NSTAGE) * STAGE_BYTES + 18432 + (wn * 32) * 144;

#pragma unroll
        for (int k16 = 0; k16 < 4; k16++) {
            uint32_t a[4][4];
#pragma unroll
            for (int mf = 0; mf < 4; mf++)
                ldsm4(a[mf], abase + (mf * 16 + lrow) * 144 + k16 * 32 + lkof);
            uint32_t b[2][4];
#pragma unroll
            for (int nf2 = 0; nf2 < 2; nf2++)
                ldsm4(b[nf2], bbase + (nf2 * 16 + lrow) * 144 + k16 * 32 + lkof);
#pragma unroll
            for (int mf = 0; mf < 4; mf++)
#pragma unroll
                for (int nf = 0; nf < 4; nf++)
                    mma16816(acc[mf][nf], a[mf], b[nf >> 1][nf & 1], b[nf >> 1][2 + (nf & 1)]);
        }
    }

    // -------- epilogue --------
    const int qr = lane >> 2;
    const int qc = (lane & 3) * 2;

    float inv[4][2];
    if (EMODE == 2) {
#pragma unroll
        for (int mf = 0; mf < 4; mf++)
#pragma unroll
            for (int h = 0; h < 2; h++)
                inv[mf][h] = 1.f / rowDiv[(size_t)batch * sSum +
                                          row0 + wm * 64 + mf * 16 + qr + h * 8];
    }
    float rsum[4][2];
    if (EMODE == 1) {
#pragma unroll
        for (int mf = 0; mf < 4; mf++)
#pragma unroll
            for (int h = 0; h < 2; h++) rsum[mf][h] = 0.f;
    }

#pragma unroll
    for (int mf = 0; mf < 4; mf++) {
#pragma unroll
        for (int nf = 0; nf < 4; nf++) {
            int gr = row0 + wm * 64 + mf * 16 + qr;
            int gc = col0 + wn * 32 + nf * 8 + qc;
            float b0 = 0.f, b1 = 0.f;
            if (bias && split == 0 && !biasRow) {
                if (gc + 0 < biasN) b0 = bias[gc + 0];
                if (gc + 1 < biasN) b1 = bias[gc + 1];
            }
#pragma unroll
            for (int h = 0; h < 2; h++) {
                int r = gr + h * 8;
                float br = (bias && split == 0 && biasRow && r < biasN) ? bias[r] : 0.f;
                float v0 = alpha * acc[mf][nf][h * 2 + 0];
                float v1 = alpha * acc[mf][nf][h * 2 + 1];
                if (EMODE == 1) {
                    v0 = __expf(v0);
                    v1 = __expf(v1);
                    rsum[mf][h] += v0 + v1;
                }
                if (EMODE == 2) { v0 *= inv[mf][h]; v1 *= inv[mf][h]; }
                v0 += b0 + br;
                v1 += b1 + br;
                if (outHalf) {
                    __half2 o;
                    o.x = __float2half(v0);
                    o.y = __float2half(v1);
                    *(__half2*)(Ch + (size_t)r * ldc + gc) = o;
                } else {
                    float* cp = Cf + (size_t)r * ldc + gc;
                    if (splitK > 1) {
                        atomicAdd(cp + 0, v0);
                        atomicAdd(cp + 1, v1);
                    } else {
                        if (accum) { v0 += cp[0]; v1 += cp[1]; }
                        float2 o = make_float2(v0, v1);
                        *(float2*)cp = o;
                    }
                }
            }
        }
    }

    if (EMODE == 1) {
#pragma unroll
        for (int mf = 0; mf < 4; mf++)
#pragma unroll
            for (int h = 0; h < 2; h++) {
                float s = rsum[mf][h];
                s += __shfl_xor_sync(0xffffffffu, s, 1);
                s += __shfl_xor_sync(0xffffffffu, s, 2);
                if ((lane & 3) == 0) {
                    int r = row0 + wm * 64 + mf * 16 + qr + h * 8;
                    atomicAdd(expSum + (size_t)batch * sSum + r, s);
                }
            }
    }
}

// ===========================================================================
// Conversion kernels
// ===========================================================================
__global__ void ext_rows(const float* __restrict__ in, __half* __restrict__ out,
                         int Kin, int ldin, int Kp, int terms, int loIdx)
{
    int c = blockIdx.x * 256 + threadIdx.x;
    if (c >= Kp) return;
    size_t row = blockIdx.y;
    int b = c / Kin;
    __half r;
    if (b >= terms) r = __float2half(0.f);
    else {
        float f = in[row * ldin + (c - b * Kin)];
        r = (b == loIdx) ? h_lo(f) : h_hi(f);
    }
    out[row * (size_t)Kp + c] = r;
}

// B-side transpose expansion with optional head remap:
// hs>0: out row n sources in column (n/hs)*hd + (n%hs), zero if (n%hs)>=hd.
__global__ void ext_transpose(const float* __restrict__ in, __half* __restrict__ out,
                              int Kin, int Nn, int Np, int Kp, int ldw,
                              long long sIn, long long sOut, int terms, int loIdx,
                              int hd, int hs)
{
    __shared__ float t[32][33];
    int b = blockIdx.z % terms, z = blockIdx.z / terms;
    in  += (size_t)z * sIn;
    out += (size_t)z * sOut;
    int k0 = blockIdx.x * 32, n0 = blockIdx.y * 32;
    int tx = threadIdx.x, ty = threadIdx.y;   // 32 x 8
#pragma unroll
    for (int i = 0; i < 4; i++) {
        int k = k0 + ty + i * 8, n = n0 + tx;
        int col; bool valid;
        if (hs > 0) {
            int dd = n % hs;
            col = (n / hs) * hd + dd;
            valid = (dd < hd) && (col < Nn);
        } else {
            col = n;
            valid = n < Nn;
        }
        t[ty + i * 8][tx] = (k < Kin && valid) ? in[(size_t)k * ldw + col] : 0.f;
    }
    __syncthreads();
#pragma unroll
    for (int i = 0; i < 4; i++) {
        int n = n0 + ty + i * 8, k = k0 + tx;
        if (n < Np && k < Kin) {
            float f = t[tx][ty + i * 8];
            out[(size_t)n * Kp + (size_t)b * Kin + k] = (b == loIdx) ? h_lo(f) : h_hi(f);
        }
    }
}

// Remap wq_b / wk_b into head-padded layout: rb[0:256]=wq_b, rb[256:512]=wk_b.
__global__ void bias_remap(const float* __restrict__ bq, const float* __restrict__ bk,
                           float* __restrict__ rb)
{
    int n = threadIdx.x;            // 256
    int dd = n & 63, h = n >> 6;
    float vq = (dd < HD) ? bq[h * HD + dd] : 0.f;
    float vk = (dd < HD) ? bk[h * HD + dd] : 0.f;
    rb[n] = vq;
    rb[256 + n] = vk;
}

// fp32 -> fp16 cast (vectorized, 4 elem/thread), total % 1024 == 0.
__global__ void cast_f2h(const float* __restrict__ in, __half* __restrict__ out)
{
    int i = (blockIdx.x * 256 + threadIdx.x) * 4;
    float4 v = *(const float4*)(in + i);
    *(__half2*)(out + i)     = __floats2half2_rn(v.x, v.y);
    *(__half2*)(out + i + 2) = __floats2half2_rn(v.z, v.w);
}

// LayerNorm (row of 3584) fused with 1-term fp16 write into [*,3584].
__global__ __launch_bounds__(256)
void ln_ext(const float* __restrict__ X, __half* __restrict__ out,
            const float* __restrict__ g, const float* __restrict__ b)
{
    const int D = LD;
    const float* p = X + (size_t)blockIdx.x * D;
    __half* q = out + (size_t)blockIdx.x * D;
    const int t = threadIdx.x;
    float v[14];
    float s = 0.f;
#pragma unroll
    for (int i = 0; i < 14; i++) { v[i] = p[t + i * 256]; s += v[i]; }
    __shared__ float red[256];
    red[t] = s; __syncthreads();
#pragma unroll
    for (int st = 128; st > 0; st >>= 1) { if (t < st) red[t] += red[t + st]; __syncthreads(); }
    const float mean = red[0] / (float)D; __syncthreads();
    float sq = 0.f;
#pragma unroll
    for (int i = 0; i < 14; i++) { float d = v[i] - mean; sq += d * d; }
    red[t] = sq; __syncthreads();
#pragma unroll
    for (int st = 128; st > 0; st >>= 1) { if (t < st) red[t] += red[t + st]; __syncthreads(); }
    const float inv = rsqrtf(red[0] / (float)D + 1e-5f);
#pragma unroll
    for (int i = 0; i < 14; i++) {
        int c = t + i * 256;
        float y = (v[i] - mean) * inv * g[c] + b[c];
        q[c] = __float2half(y);
    }
}

// ===========================================================================
// Launcher — R14 schedule (empirical best): fork/join, scores M-split
// overlapped with ctx, ln_A/out_A on s1 overlapping ctx_B.
// ===========================================================================
extern "C" void kernel_launch(void* const* d_in, const int* in_sizes, int n_in,
                              void* d_out, int out_size)
{
    const float* target  = (const float*)d_in[0];
    const float* source  = (const float*)d_in[1];
    const float* value   = (const float*)d_in[2];
    const float* wq_w    = (const float*)d_in[3];
    const float* wq_b    = (const float*)d_in[4];
    const float* wk_w    = (const float*)d_in[5];
    const float* wk_b    = (const float*)d_in[6];
    const float* wv_w    = (const float*)d_in[7];
    const float* wv_b    = (const float*)d_in[8];
    const float* resid_w = (const float*)d_in[9];
    const float* resid_b = (const float*)d_in[10];
    const float* out_w   = (const float*)d_in[11];
    const float* out_b   = (const float*)d_in[12];
    const float* ln_g    = (const float*)d_in[13];
    const float* ln_b    = (const float*)d_in[14];
    float* out = (float*)d_out;

    __half *pte, *pse, *pve, *pwqe, *pwke, *pwve, *pre, *poe;
    __half *pQe, *pKe, *pS, *pVte, *pXe;
    float *pKf, *pXf, *pSum, *prb;
    cudaGetSymbolAddress((void**)&pte, g_te);
    cudaGetSymbolAddress((void**)&pse, g_se);
    cudaGetSymbolAddress((void**)&pve, g_ve);
    cudaGetSymbolAddress((void**)&pwqe, g_wqe);
    cudaGetSymbolAddress((void**)&pwke, g_wke);
    cudaGetSymbolAddress((void**)&pwve, g_wve);
    cudaGetSymbolAddress((void**)&pre, g_re);
    cudaGetSymbolAddress((void**)&poe, g_oe);
    cudaGetSymbolAddress((void**)&prb, g_rb);
    cudaGetSymbolAddress((void**)&pKf, g_Kf);
    cudaGetSymbolAddress((void**)&pQe, g_Qe);
    cudaGetSymbolAddress((void**)&pKe, g_Ke);
    cudaGetSymbolAddress((void**)&pS, g_S);
    cudaGetSymbolAddress((void**)&pSum, g_sum);
    cudaGetSymbolAddress((void**)&pVte, g_Vte);
    cudaGetSymbolAddress((void**)&pXf, g_Xf);
    cudaGetSymbolAddress((void**)&pXe, g_Xe);

    cudaFuncSetAttribute(mma_gemm<0>, cudaFuncAttributeMaxDynamicSharedMemorySize, MMA_SMEM);
    cudaFuncSetAttribute(mma_gemm<1>, cudaFuncAttributeMaxDynamicSharedMemorySize, MMA_SMEM);
    cudaFuncSetAttribute(mma_gemm<2>, cudaFuncAttributeMaxDynamicSharedMemorySize, MMA_SMEM);

    static cudaStream_t s1 = 0, s2 = 0;
    static cudaEvent_t evFork = 0, evQp = 0, evResid = 0, evOE = 0, evVt = 0;
    static cudaEvent_t evScA = 0, evCtxA = 0, evOutA = 0;
    if (!evFork) {
        cudaStreamCreateWithFlags(&s1, cudaStreamNonBlocking);
        cudaStreamCreateWithFlags(&s2, cudaStreamNonBlocking);
        cudaEventCreateWithFlags(&evFork, cudaEventDisableTiming);
        cudaEventCreateWithFlags(&evQp, cudaEventDisableTiming);
        cudaEventCreateWithFlags(&evResid, cudaEventDisableTiming);
        cudaEventCreateWithFlags(&evOE, cudaEventDisableTiming);
        cudaEventCreateWithFlags(&evVt, cudaEventDisableTiming);
        cudaEventCreateWithFlags(&evScA, cudaEventDisableTiming);
        cudaEventCreateWithFlags(&evCtxA, cudaEventDisableTiming);
        cudaEventCreateWithFlags(&evOutA, cudaEventDisableTiming);
    }

    // ---- fork ----
    cudaEventRecord(evFork, 0);
    cudaStreamWaitEvent(s1, evFork, 0);
    cudaStreamWaitEvent(s2, evFork, 0);

    // ===== stream s1: Q chain (head layout), resid chain, out_w ext ========
    cudaMemsetAsync(pwqe, 0, (size_t)256 * KP_RD * sizeof(__half), s1);
    cudaMemsetAsync(pre, 0, (size_t)LD * KP_RD * sizeof(__half), s1);
    ext_rows<<<dim3(2, NQ), 256, 0, s1>>>(target, pte, RD, RD, KP_RD, 2, 1);
    ext_transpose<<<dim3(5, 8, 2), dim3(32, 8), 0, s1>>>(
        wq_w, pwqe, RD, RD, 256, KP_RD, RD, 0, 0, 2, -1, HD, 64);          // head remap
    bias_remap<<<1, 256, 0, s1>>>(wq_b, wk_b, prb);
    mma_gemm<0><<<dim3(2, 32, 1), 256, MMA_SMEM, s1>>>(
        pte, pwqe, pQe, KP_RD, KP_RD, KP_RD, 256, 0, 0, 0, 1.f, prb, 256, 0, 0, 1, 1, 0,
        nullptr, nullptr, 0);                                              // fp16 head layout
    cudaEventRecord(evQp, s1);
    ext_transpose<<<dim3(5, 112, 2), dim3(32, 8), 0, s1>>>(
        resid_w, pre, RD, LD, LD, KP_RD, LD, 0, 0, 2, -1, 0, 0);
    mma_gemm<0><<<dim3(28, 32, 1), 256, MMA_SMEM, s1>>>(
        pte, pre, pXf, KP_RD, KP_RD, KP_RD, LD, 0, 0, 0, 1.f, resid_b, LD, 0, 0, 1, 0, 0,
        nullptr, nullptr, 0);
    cudaEventRecord(evResid, s1);
    ext_transpose<<<dim3(112, 112, 1), dim3(32, 8), 0, s1>>>(
        out_w, poe, LD, LD, LD, LD, LD, 0, 0, 1, -1, 0, 0);
    cudaEventRecord(evOE, s1);

    // ===== stream s2: V chain (direct V^T, single 896-CTA GEMM) ===========
    cast_f2h<<<14336, 256, 0, s2>>>(value, pve);                           // vectorized cast
    ext_transpose<<<dim3(112, 28, 4), dim3(32, 8), 0, s2>>>(
        wv_w, pwve, LD, VHD, VHD, LD, VHD,
        (long long)LD * VHD, (long long)VHD * LD, 1, -1, 0, 0);
    mma_gemm<0><<<dim3(32, 7, NH), 256, MMA_SMEM, s2>>>(
        pwve, pve, pVte, LD, LD, LD, NQ,
        (long long)VHD * LD, 0, (long long)VHD * NQ,
        1.f, wv_b, VHD, VHD, 0, 1, 1, 1,
        nullptr, nullptr, 0);
    cudaEventRecord(evVt, s2);

    // ===== default stream: K chain + scores =====
    cudaMemsetAsync(pKf, 0, (size_t)NQ * 256 * sizeof(float), 0);
    cudaMemsetAsync(pSum, 0, (size_t)NH * NQ * sizeof(float), 0);
    cast_f2h<<<14336, 256, 0, 0>>>(source, pse);                           // vectorized cast
    ext_transpose<<<dim3(112, 8, 1), dim3(32, 8), 0, 0>>>(
        wk_w, pwke, LD, RD, 256, LD, RD, 0, 0, 1, -1, HD, 64);             // head remap
    mma_gemm<0><<<dim3(2, 32, 4), 256, MMA_SMEM, 0>>>(
        pse, pwke, pKf, LD, LD, LD, 256, 0, 0, 0, 1.f, prb + 256, 256, 0, 0, 4, 0, 0,
        nullptr, nullptr, 0);
    cast_f2h<<<NQ, 256, 0, 0>>>(pKf, pKe);

    cudaStreamWaitEvent(0, evQp, 0);
    // scores_A: rows 0..2047 — S = exp(QK/6), atomic rowsums
    mma_gemm<1><<<dim3(32, 16, NH), 256, MMA_SMEM, 0>>>(
        pQe, pKe, pS, KP_HD, 256, 256, NQ,
        64, 64, (long long)NQ * NQ,
        1.f / 6.f, nullptr, 0, 0, 0, 1, 1, 0,
        pSum, nullptr, NQ);
    cudaEventRecord(evScA, 0);
    // scores_B: rows 2048..4095 (overlaps ctx_A on s2)
    mma_gemm<1><<<dim3(32, 16, NH), 256, MMA_SMEM, 0>>>(
        pQe + (size_t)2048 * 256, pKe, pS + (size_t)2048 * NQ, KP_HD, 256, 256, NQ,
        64, 64, (long long)NQ * NQ,
        1.f / 6.f, nullptr, 0, 0, 0, 1, 1, 0,
        pSum + 2048, nullptr, NQ);

    // ===== s2: ctx_A (rows 0..2047) overlapping scores_B =====
    cudaStreamWaitEvent(s2, evScA, 0);
    cudaStreamWaitEvent(s2, evResid, 0);
    mma_gemm<2><<<dim3(7, 16, NH), 256, MMA_SMEM, s2>>>(
        pS, pVte, pXf, NQ, NQ, NQ, LD,
        (long long)NQ * NQ, (long long)VHD * NQ, (long long)VHD,
        1.f, nullptr, 0, 0, 1, 1, 0, 0,
        nullptr, pSum, NQ);
    cudaEventRecord(evCtxA, s2);

    // ===== default stream: ctx_B =====
    cudaStreamWaitEvent(0, evVt, 0);
    cudaStreamWaitEvent(0, evResid, 0);
    mma_gemm<2><<<dim3(7, 16, NH), 256, MMA_SMEM, 0>>>(
        pS + (size_t)2048 * NQ, pVte, pXf + (size_t)2048 * LD, NQ, NQ, NQ, LD,
        (long long)NQ * NQ, (long long)VHD * NQ, (long long)VHD,
        1.f, nullptr, 0, 0, 1, 1, 0, 0,
        nullptr, pSum + 2048, NQ);

    // ===== s1: ln_A + out_A overlap ctx_B =====
    cudaStreamWaitEvent(s1, evCtxA, 0);
    ln_ext<<<2048, 256, 0, s1>>>(pXf, pXe, ln_g, ln_b);
    mma_gemm<0><<<dim3(28, 16, 1), 256, MMA_SMEM, s1>>>(
        pXe, poe, out, LD, LD, LD, LD, 0, 0, 0, 1.f, out_b, LD, 0, 0, 1, 0, 0,
        nullptr, nullptr, 0);
    cudaEventRecord(evOutA, s1);

    // ===== default stream: ln_B + out_B =====
    ln_ext<<<2048, 256, 0, 0>>>(pXf + (size_t)2048 * LD, pXe + (size_t)2048 * LD, ln_g, ln_b);
    cudaStreamWaitEvent(0, evOE, 0);
    mma_gemm<0><<<dim3(28, 16, 1), 256, MMA_SMEM, 0>>>(
        pXe + (size_t)2048 * LD, poe, out + (size_t)2048 * LD, LD, LD, LD, LD,
        0, 0, 0, 1.f, out_b, LD, 0, 0, 1, 0, 0,
        nullptr, nullptr, 0);

    // ---- join ----
    cudaStreamWaitEvent(0, evOutA, 0);
}